// round 1
// baseline (speedup 1.0000x reference)
#include <cuda_runtime.h>
#include <math.h>

// GraphQNN: h = tanh(W @ x); exp_val computed analytically.
//
// Heisenberg-picture reduction of <Z_0> through the circuit:
//   layer-1 CNOT chain: Z_0 invariant (Z on control commutes with CNOT)
//   layer-1 RZ(phi')RX(theta') on qubit 0: Z -> cos(t')Z + sin(t')Y,  t' = q_params[46]
//   layer-0 CNOT chain: Z_0 -> Z_0 ; Y_0 -> Y_0 X_1
//   product state per qubit: |psi_q> = RZ(phi_q) RX(theta_q) RY(2 h_q)|0>
//   Bloch components:
//     <Z>_0 = cos(t0) cos(2 h0)
//     <Y>_0 = sin(p0) sin(2 h0) - cos(p0) sin(t0) cos(2 h0)
//     <X>_1 = cos(p1) sin(2 h1) + sin(p1) sin(t1) cos(2 h1)
//   exp_val = cos(t') <Z>_0 + sin(t') <Y>_0 <X>_1

#define NQ 23
#define IN_DIM 1024

__global__ void __launch_bounds__(NQ * 32)
graphqnn_kernel(const float* __restrict__ x,
                const float* __restrict__ W,
                const float* __restrict__ qp,
                float* __restrict__ out) {
    __shared__ float h_sh[NQ];

    const int warp = threadIdx.x >> 5;
    const int lane = threadIdx.x & 31;

    // One warp per output row of W (23 warps).
    // Each lane handles 8 float4's of the 256 float4 row.
    const float4* xr = reinterpret_cast<const float4*>(x);
    const float4* wr = reinterpret_cast<const float4*>(W + warp * IN_DIM);

    float s = 0.0f;
    #pragma unroll
    for (int i = 0; i < IN_DIM / 4 / 32; ++i) {
        float4 a = wr[lane + 32 * i];
        float4 b = xr[lane + 32 * i];
        s += a.x * b.x + a.y * b.y + a.z * b.z + a.w * b.w;
    }
    #pragma unroll
    for (int o = 16; o > 0; o >>= 1)
        s += __shfl_xor_sync(0xffffffffu, s, o);

    if (lane == 0) {
        float h = tanhf(s);
        out[warp] = h;
        h_sh[warp] = h;
    }
    __syncthreads();

    if (threadIdx.x == 0) {
        double h0 = (double)h_sh[0];
        double h1 = (double)h_sh[1];
        double t0 = (double)qp[0];   // layer 0, qubit 0, RX angle
        double p0 = (double)qp[1];   // layer 0, qubit 0, RZ angle
        double t1 = (double)qp[2];   // layer 0, qubit 1, RX angle
        double p1 = (double)qp[3];   // layer 0, qubit 1, RZ angle
        double tp = (double)qp[2 * NQ * 1 + 0];  // q_params[46]: layer 1, qubit 0, RX angle

        double c2h0 = cos(2.0 * h0), s2h0 = sin(2.0 * h0);
        double c2h1 = cos(2.0 * h1), s2h1 = sin(2.0 * h1);

        double z0 = cos(t0) * c2h0;
        double y0 = sin(p0) * s2h0 - cos(p0) * sin(t0) * c2h0;
        double x1 = cos(p1) * s2h1 + sin(p1) * sin(t1) * c2h1;

        double ev = cos(tp) * z0 + sin(tp) * y0 * x1;
        out[NQ] = (float)ev;
    }
}

extern "C" void kernel_launch(void* const* d_in, const int* in_sizes, int n_in,
                              void* d_out, int out_size) {
    const float* x  = (const float*)d_in[0];
    const float* W  = (const float*)d_in[1];
    const float* qp = (const float*)d_in[2];
    float* out = (float*)d_out;
    graphqnn_kernel<<<1, NQ * 32>>>(x, W, qp, out);
}

// round 2
// speedup vs baseline: 2.1852x; 2.1852x over previous
#include <cuda_runtime.h>
#include <math.h>

// GraphQNN: h = tanh(W @ x); exp_val computed analytically (Heisenberg picture).
//
//   layer-1 CNOT chain: Z_0 invariant (Z on control commutes with CNOT)
//   layer-1 RZ(p')RX(t') on qubit 0: Z -> cos(t')Z + sin(t')Y,  t' = q_params[46]
//   layer-0 CNOT chain: Z_0 -> Z_0 ; Y_0 -> Y_0 X_1
//   product state per qubit: |psi_q> = RZ(phi_q) RX(theta_q) RY(2 h_q)|0>
//     <Z>_0 = cos(t0) cos(2 h0)
//     <Y>_0 = sin(p0) sin(2 h0) - cos(p0) sin(t0) cos(2 h0)
//     <X>_1 = cos(p1) sin(2 h1) + sin(p1) sin(t1) cos(2 h1)
//   exp_val = cos(t') <Z>_0 + sin(t') <Y>_0 <X>_1
//
// R2: all-float math (no FP64 software trig tail); qp trig hidden under
// the matvec's DRAM latency on thread 0.

#define NQ 23
#define IN_DIM 1024

__global__ void __launch_bounds__(NQ * 32)
graphqnn_kernel(const float* __restrict__ x,
                const float* __restrict__ W,
                const float* __restrict__ qp,
                float* __restrict__ out) {
    __shared__ float h_sh[NQ];

    const int warp = threadIdx.x >> 5;
    const int lane = threadIdx.x & 31;

    // --- issue all matvec loads first (long-latency, high MLP) ---
    const float4* xr = reinterpret_cast<const float4*>(x);
    const float4* wr = reinterpret_cast<const float4*>(W + warp * IN_DIM);

    float4 a[8], b[8];
    #pragma unroll
    for (int i = 0; i < 8; ++i) {
        a[i] = wr[lane + 32 * i];
        b[i] = xr[lane + 32 * i];
    }

    // --- qp-dependent trig on thread 0, overlapped with the loads above ---
    float ct0, st0, cp0, sp0, ct1_unused, st1, cp1, sp1, ctp, stp;
    if (threadIdx.x == 0) {
        float t0 = qp[0], p0 = qp[1], t1 = qp[2], p1 = qp[3];
        float tp = qp[2 * NQ];  // q_params[46]: layer 1, qubit 0, RX angle
        sincosf(t0, &st0, &ct0);
        sincosf(p0, &sp0, &cp0);
        st1 = sinf(t1); ct1_unused = 0.f;
        sincosf(p1, &sp1, &cp1);
        sincosf(tp, &stp, &ctp);
    }

    // --- dot product + warp reduce ---
    float s = 0.0f;
    #pragma unroll
    for (int i = 0; i < 8; ++i)
        s += a[i].x * b[i].x + a[i].y * b[i].y + a[i].z * b[i].z + a[i].w * b[i].w;

    #pragma unroll
    for (int o = 16; o > 0; o >>= 1)
        s += __shfl_xor_sync(0xffffffffu, s, o);

    if (lane == 0) {
        float h = tanhf(s);
        out[warp] = h;
        h_sh[warp] = h;
    }
    __syncthreads();

    if (threadIdx.x == 0) {
        float h0 = h_sh[0];
        float h1 = h_sh[1];

        float c2h0, s2h0, c2h1, s2h1;
        sincosf(2.0f * h0, &s2h0, &c2h0);
        sincosf(2.0f * h1, &s2h1, &c2h1);

        float z0 = ct0 * c2h0;
        float y0 = sp0 * s2h0 - cp0 * st0 * c2h0;
        float x1 = cp1 * s2h1 + sp1 * st1 * c2h1;

        out[NQ] = ctp * z0 + stp * y0 * x1;
    }
}

extern "C" void kernel_launch(void* const* d_in, const int* in_sizes, int n_in,
                              void* d_out, int out_size) {
    const float* x  = (const float*)d_in[0];
    const float* W  = (const float*)d_in[1];
    const float* qp = (const float*)d_in[2];
    float* out = (float*)d_out;
    graphqnn_kernel<<<1, NQ * 32>>>(x, W, qp, out);
}

// round 3
// speedup vs baseline: 2.2692x; 1.0385x over previous
#include <cuda_runtime.h>
#include <math.h>

// GraphQNN: h = tanh(W @ x); exp_val computed analytically (Heisenberg picture).
//
//   layer-1 CNOT chain: Z_0 invariant (Z on control commutes with CNOT)
//   layer-1 RZ(p')RX(t') on qubit 0: Z -> cos(t')Z + sin(t')Y,  t' = q_params[46]
//   layer-0 CNOT chain: Z_0 -> Z_0 ; Y_0 -> Y_0 X_1
//   product state per qubit: |psi_q> = RZ(phi_q) RX(theta_q) RY(2 h_q)|0>
//     <Z>_0 = cos(t0) cos(2 h0)
//     <Y>_0 = sin(p0) sin(2 h0) - cos(p0) sin(t0) cos(2 h0)
//     <X>_1 = cos(p1) sin(2 h1) + sin(p1) sin(t1) cos(2 h1)
//   exp_val = cos(t') <Z>_0 + sin(t') <Y>_0 <X>_1
//
// R3: multi-SM. 12 blocks x 512 threads; block b computes rows 2b and 2b+1
// (256 threads per row, one float4 of W and x per thread). Block 0 owns rows
// 0 and 1 -- exactly the h-values exp_val needs -- so the scalar tail is
// block-local. Spreads ~1472 L1tex wavefronts across 12 SMs instead of 1.

#define NQ 23
#define IN_DIM 1024

__global__ void __launch_bounds__(512)
graphqnn_kernel(const float* __restrict__ x,
                const float* __restrict__ W,
                const float* __restrict__ qp,
                float* __restrict__ out) {
    __shared__ float warp_sums[16];
    __shared__ float h01[2];

    const int tid  = threadIdx.x;
    const int g    = tid >> 8;        // row-group within block: 0 or 1
    const int t    = tid & 255;       // thread within group
    const int row  = 2 * blockIdx.x + g;
    const bool active = (row < NQ);

    // one float4 of W-row and x per thread
    float s = 0.0f;
    if (active) {
        float4 a = reinterpret_cast<const float4*>(W + row * IN_DIM)[t];
        float4 b = reinterpret_cast<const float4*>(x)[t];
        s = a.x * b.x + a.y * b.y + a.z * b.z + a.w * b.w;
    }

    // qp trig on block 0 / thread 0, overlapped with the loads above
    float ct0, st0, cp0, sp0, st1, cp1, sp1, ctp, stp;
    if (blockIdx.x == 0 && tid == 0) {
        sincosf(qp[0], &st0, &ct0);    // t0: layer 0, qubit 0, RX
        sincosf(qp[1], &sp0, &cp0);    // p0: layer 0, qubit 0, RZ
        st1 = sinf(qp[2]);             // t1: layer 0, qubit 1, RX
        sincosf(qp[3], &sp1, &cp1);    // p1: layer 0, qubit 1, RZ
        sincosf(qp[2 * NQ], &stp, &ctp); // t': layer 1, qubit 0, RX
    }

    // intra-warp reduce
    #pragma unroll
    for (int o = 16; o > 0; o >>= 1)
        s += __shfl_xor_sync(0xffffffffu, s, o);
    const int warp = tid >> 5;
    if ((tid & 31) == 0) warp_sums[warp] = s;
    __syncthreads();

    // warp 0 of each group reduces its 8 partials
    if ((tid & 255) < 32) {
        const int lane = tid & 31;
        float v = (lane < 8) ? warp_sums[g * 8 + lane] : 0.0f;
        #pragma unroll
        for (int o = 4; o > 0; o >>= 1)
            v += __shfl_xor_sync(0xffffffffu, v, o);
        if (lane == 0 && active) {
            float h = tanhf(v);
            out[row] = h;
            if (blockIdx.x == 0) h01[g] = h;
        }
    }

    if (blockIdx.x == 0) {
        __syncthreads();
        if (tid == 0) {
            float c2h0, s2h0, c2h1, s2h1;
            sincosf(2.0f * h01[0], &s2h0, &c2h0);
            sincosf(2.0f * h01[1], &s2h1, &c2h1);
            float z0 = ct0 * c2h0;
            float y0 = sp0 * s2h0 - cp0 * st0 * c2h0;
            float x1 = cp1 * s2h1 + sp1 * st1 * c2h1;
            out[NQ] = ctp * z0 + stp * y0 * x1;
        }
    }
}

extern "C" void kernel_launch(void* const* d_in, const int* in_sizes, int n_in,
                              void* d_out, int out_size) {
    const float* x  = (const float*)d_in[0];
    const float* W  = (const float*)d_in[1];
    const float* qp = (const float*)d_in[2];
    float* out = (float*)d_out;
    graphqnn_kernel<<<(NQ + 1) / 2, 512>>>(x, W, qp, out);
}

// round 4
// speedup vs baseline: 2.2913x; 1.0097x over previous
#include <cuda_runtime.h>
#include <math.h>

// GraphQNN: h = tanh(W @ x); exp_val computed analytically (Heisenberg picture).
//
//   layer-1 CNOT chain: Z_0 invariant; layer-1 RX(t') on q0: Z -> cos t' Z + sin t' Y
//   layer-0 CNOT chain: Z_0 -> Z_0 ; Y_0 -> Y_0 X_1
//   product state per qubit q: RZ(p_q) RX(t_q) RY(2 h_q)|0>
//     <Z>_0 = cos t0 cos 2h0
//     <Y>_0 = sin p0 sin 2h0 - cos p0 sin t0 cos 2h0
//     <X>_1 = cos p1 sin 2h1 + sin p1 sin t1 cos 2h1
//   exp_val = cos t' <Z>_0 + sin t' <Y>_0 <X>_1     (t' = q_params[46])
//
// R4: zero barriers, zero smem. Warps 0-22: one h-row each (warp reduce only).
// Warp 23: redundantly computes rows 0 and 1 (half-warp each) and the scalar
// tail with fast-math trig -- fully independent of the other warps.

#define NQ 23
#define IN_DIM 1024

__global__ void __launch_bounds__((NQ + 1) * 32)
graphqnn_kernel(const float* __restrict__ x,
                const float* __restrict__ W,
                const float* __restrict__ qp,
                float* __restrict__ out) {
    const int warp = threadIdx.x >> 5;
    const int lane = threadIdx.x & 31;

    const float4* xr = reinterpret_cast<const float4*>(x);

    if (warp < NQ) {
        // ---- h-row warp: 1024-dot, 8 float4 per lane, 4 accumulators ----
        const float4* wr = reinterpret_cast<const float4*>(W + warp * IN_DIM);
        float4 a[8], b[8];
        #pragma unroll
        for (int i = 0; i < 8; ++i) { a[i] = wr[lane + 32 * i]; b[i] = xr[lane + 32 * i]; }

        float s0 = 0.f, s1 = 0.f, s2 = 0.f, s3 = 0.f;
        #pragma unroll
        for (int i = 0; i < 8; i += 4) {
            s0 += a[i+0].x*b[i+0].x + a[i+0].y*b[i+0].y + a[i+0].z*b[i+0].z + a[i+0].w*b[i+0].w;
            s1 += a[i+1].x*b[i+1].x + a[i+1].y*b[i+1].y + a[i+1].z*b[i+1].z + a[i+1].w*b[i+1].w;
            s2 += a[i+2].x*b[i+2].x + a[i+2].y*b[i+2].y + a[i+2].z*b[i+2].z + a[i+2].w*b[i+2].w;
            s3 += a[i+3].x*b[i+3].x + a[i+3].y*b[i+3].y + a[i+3].z*b[i+3].z + a[i+3].w*b[i+3].w;
        }
        float s = (s0 + s1) + (s2 + s3);
        #pragma unroll
        for (int o = 16; o > 0; o >>= 1)
            s += __shfl_xor_sync(0xffffffffu, s, o);
        if (lane == 0) out[warp] = tanhf(s);
    } else {
        // ---- tail warp: lanes 0-15 -> row 0 dot, lanes 16-31 -> row 1 dot ----
        const int half = lane >> 4;          // 0 or 1 = row
        const int hl   = lane & 15;          // lane within half
        const float4* wr = reinterpret_cast<const float4*>(W + half * IN_DIM);

        float s0 = 0.f, s1 = 0.f;
        #pragma unroll
        for (int i = 0; i < 16; i += 2) {
            float4 a0 = wr[hl + 16 * (i+0)], b0 = xr[hl + 16 * (i+0)];
            float4 a1 = wr[hl + 16 * (i+1)], b1 = xr[hl + 16 * (i+1)];
            s0 += a0.x*b0.x + a0.y*b0.y + a0.z*b0.z + a0.w*b0.w;
            s1 += a1.x*b1.x + a1.y*b1.y + a1.z*b1.z + a1.w*b1.w;
        }
        float s = s0 + s1;
        // reduce within each 16-lane half
        #pragma unroll
        for (int o = 8; o > 0; o >>= 1)
            s += __shfl_xor_sync(0xffffffffu, s, o);

        float h  = tanhf(s);                              // lane0: h0, lane16: h1
        float hо = __shfl_sync(0xffffffffu, h, 16);       // h1 (valid in lane 0)

        if (lane == 0) {
            float h0 = h, h1 = hо;
            float ct0, st0, cp0, sp0, st1, cp1, sp1, ctp, stp;
            __sincosf(qp[0], &st0, &ct0);       // t0
            __sincosf(qp[1], &sp0, &cp0);       // p0
            st1 = __sinf(qp[2]);                // t1
            __sincosf(qp[3], &sp1, &cp1);       // p1
            __sincosf(qp[2 * NQ], &stp, &ctp);  // t' = q_params[46]

            float c2h0, s2h0, c2h1, s2h1;
            __sincosf(2.0f * h0, &s2h0, &c2h0);
            __sincosf(2.0f * h1, &s2h1, &c2h1);

            float z0 = ct0 * c2h0;
            float y0 = sp0 * s2h0 - cp0 * st0 * c2h0;
            float x1 = cp1 * s2h1 + sp1 * st1 * c2h1;
            out[NQ] = ctp * z0 + stp * y0 * x1;
        }
    }
}

extern "C" void kernel_launch(void* const* d_in, const int* in_sizes, int n_in,
                              void* d_out, int out_size) {
    const float* x  = (const float*)d_in[0];
    const float* W  = (const float*)d_in[1];
    const float* qp = (const float*)d_in[2];
    float* out = (float*)d_out;
    graphqnn_kernel<<<1, (NQ + 1) * 32>>>(x, W, qp, out);
}